// round 15
// baseline (speedup 1.0000x reference)
#include <cuda_runtime.h>
#include <cuda_fp16.h>
#include <cstdint>

#define T_TOKENS 1024
#define IN_DIM   4096
#define Q_DIM    4096
#define KV_DIM   1024
#define OUT_DIM  6144
#define NUM_D    4

#define BM 64
#define BN 192
#define KC 64
#define NCHUNK (IN_DIM / KC)     // 64
#define NTILE  (T_TOKENS / BM)   // 16 row tiles per adapter

#define XP_ROWS (T_TOKENS + BM)  // 1088 padded rows per adapter

#define ASTRIDE 144              // bytes per smem tile row (128 data + 16 pad)
#define TILE_A  (64 * ASTRIDE)   // 9216
#define TILE_BB (192 * ASTRIDE)  // 27648
#define STAGE_B (TILE_A + TILE_BB) // 36864
#define SM_MISC 4096
#define SMEM_TOTAL (SM_MISC + 2 * STAGE_B)   // 77824

__device__ int    g_cnt[NUM_D];
__device__ int    g_perm[NUM_D][T_TOKENS];
__device__ float  g_rowsum[T_TOKENS];
__device__ __half g_wc[(size_t)NUM_D * OUT_DIM * IN_DIM];   // fp16 combined weights
__device__ __half g_xp[(size_t)NUM_D * XP_ROWS * IN_DIM];   // fp16 permuted x

// ---------------- setup: reset + adapter grouping in one block -------------

__global__ void __launch_bounds__(1024)
setup_kernel(const int* __restrict__ indices) {
    __shared__ int scnt[NUM_D];
    const int t = threadIdx.x;
    if (t < NUM_D) scnt[t] = 0;
    __syncthreads();
    const int d = indices[t];
    const int pos = atomicAdd(&scnt[d], 1);
    g_perm[d][pos] = t;
    __syncthreads();
    if (t < NUM_D) g_cnt[t] = scnt[t];
}

// ------------------------------ helpers -----------------------------------

__device__ __forceinline__ uint32_t smem_u32(const void* p) {
    uint32_t a;
    asm("{ .reg .u64 t; cvta.to.shared.u64 t, %1; cvt.u32.u64 %0, t; }"
        : "=r"(a) : "l"(p));
    return a;
}

__device__ __forceinline__ uint32_t h2pack(float a, float b) {
    __half2 h = __float22half2_rn(make_float2(a, b));
    return *(uint32_t*)&h;
}

__device__ __forceinline__ void cpa16(uint32_t dst, const void* src) {
    asm volatile("cp.async.ca.shared.global [%0], [%1], 16;"
                 :: "r"(dst), "l"(src) : "memory");
}

__device__ __forceinline__ void ldsm4(uint32_t* r, uint32_t addr) {
    asm volatile("ldmatrix.sync.aligned.m8n8.x4.shared.b16 {%0,%1,%2,%3}, [%4];"
                 : "=r"(r[0]), "=r"(r[1]), "=r"(r[2]), "=r"(r[3]) : "r"(addr));
}

__device__ __forceinline__ void mma16816(float* c, const uint32_t* a,
                                         uint32_t b0, uint32_t b1) {
    asm volatile(
        "mma.sync.aligned.m16n8k16.row.col.f32.f16.f16.f32 "
        "{%0,%1,%2,%3}, {%4,%5,%6,%7}, {%8,%9}, {%0,%1,%2,%3};"
        : "+f"(c[0]), "+f"(c[1]), "+f"(c[2]), "+f"(c[3])
        : "r"(a[0]), "r"(a[1]), "r"(a[2]), "r"(a[3]), "r"(b0), "r"(b1));
}

// ---------------- precompute: fp16 combined weights ------------------------

__global__ void __launch_bounds__(256)
conv_w_kernel(const float* __restrict__ w_base,
              const int* __restrict__ qw_q, const int* __restrict__ qw_k,
              const int* __restrict__ qw_v,
              const float* __restrict__ sc_q, const float* __restrict__ sc_k,
              const float* __restrict__ sc_v)
{
    const int o = blockIdx.x;
    const int t = threadIdx.x;
    const float4* wrow = (const float4*)(w_base + (size_t)o * IN_DIM);

    int ol; const int* qws; const float* scs; size_t dq; int ds;
    if (o < Q_DIM) {
        ol = o; qws = qw_q; scs = sc_q; dq = (size_t)Q_DIM * (IN_DIM / 8); ds = Q_DIM;
    } else if (o < Q_DIM + KV_DIM) {
        ol = o - Q_DIM; qws = qw_k; scs = sc_k; dq = (size_t)KV_DIM * (IN_DIM / 8); ds = KV_DIM;
    } else {
        ol = o - Q_DIM - KV_DIM; qws = qw_v; scs = sc_v; dq = (size_t)KV_DIM * (IN_DIM / 8); ds = KV_DIM;
    }

    float4 w[2][2];
    #pragma unroll
    for (int i = 0; i < 2; i++) {
        const int g8 = t + 256 * i;
        w[i][0] = wrow[2 * g8];
        w[i][1] = wrow[2 * g8 + 1];
    }

    #pragma unroll
    for (int d = 0; d < NUM_D; d++) {
        const int* qrow = qws + d * dq + (size_t)ol * (IN_DIM / 8);
        const float s = scs[d * ds + ol];
        __half* dst = g_wc + ((size_t)d * OUT_DIM + o) * IN_DIM;
        #pragma unroll
        for (int i = 0; i < 2; i++) {
            const int g8 = t + 256 * i;
            const int q  = qrow[g8];
            float e0 = fmaf(s, (float)((q      ) & 0xF), w[i][0].x);
            float e1 = fmaf(s, (float)((q >>  4) & 0xF), w[i][0].y);
            float e2 = fmaf(s, (float)((q >>  8) & 0xF), w[i][0].z);
            float e3 = fmaf(s, (float)((q >> 12) & 0xF), w[i][0].w);
            float e4 = fmaf(s, (float)((q >> 16) & 0xF), w[i][1].x);
            float e5 = fmaf(s, (float)((q >> 20) & 0xF), w[i][1].y);
            float e6 = fmaf(s, (float)((q >> 24) & 0xF), w[i][1].z);
            float e7 = fmaf(s, (float)((q >> 28) & 0xF), w[i][1].w);
            uint4 b;
            b.x = h2pack(e0, e1);
            b.y = h2pack(e2, e3);
            b.z = h2pack(e4, e5);
            b.w = h2pack(e6, e7);
            *(uint4*)(dst + (size_t)g8 * 8) = b;
        }
    }
}

// -------- precompute: fp16 permuted activations + fused rowsum -------------

__global__ void __launch_bounds__(256)
conv_x_kernel(const float* __restrict__ x)
{
    const int d = blockIdx.y;
    const int r = blockIdx.x;
    const int cnt  = g_cnt[d];
    const int rcap = (cnt + BM - 1) & ~(BM - 1);
    if (r >= rcap) return;
    const int t = threadIdx.x;
    __half* dst = g_xp + ((size_t)d * XP_ROWS + r) * IN_DIM;
    if (r < cnt) {
        const int tok = g_perm[d][r];
        const float4* src = (const float4*)(x + (size_t)tok * IN_DIM);
        float s = 0.f;
        #pragma unroll
        for (int i = 0; i < 4; i++) {
            float4 v = src[t + 256 * i];
            s += (v.x + v.y) + (v.z + v.w);
            uint2 p;
            p.x = h2pack(v.x, v.y);
            p.y = h2pack(v.z, v.w);
            *(uint2*)(dst + (size_t)(t + 256 * i) * 4) = p;
        }
        __shared__ float red[8];
        #pragma unroll
        for (int off = 16; off > 0; off >>= 1)
            s += __shfl_down_sync(0xffffffffu, s, off);
        if ((t & 31) == 0) red[t >> 5] = s;
        __syncthreads();
        if (t == 0) {
            float tot = 0.f;
            #pragma unroll
            for (int wq = 0; wq < 8; wq++) tot += red[wq];
            g_rowsum[tok] = tot;
        }
    } else {
        #pragma unroll
        for (int i = 0; i < 4; i++)
            *(uint2*)(dst + (size_t)(t + 256 * i) * 4) = make_uint2(0, 0);
    }
}

// --------------------------- main fp16 grouped GEMM ------------------------
// 64(M) x 192(N) tile, KC=64, 2-stage cp.async pipeline, 2 blocks/SM.
// warps 2(M) x 4(N), warp tile 32x48. Per-column Q/K/V segment resolution.

__global__ void __launch_bounds__(256, 2)
fused_qkv_delta_mma(
    const float* __restrict__ bias,
    const int* __restrict__ qz_q, const int* __restrict__ qz_k, const int* __restrict__ qz_v,
    const float* __restrict__ sc_q, const float* __restrict__ sc_k, const float* __restrict__ sc_v,
    float* __restrict__ out)
{
    const int d      = blockIdx.y / NTILE;
    const int tile   = blockIdx.y % NTILE;
    const int cnt    = g_cnt[d];
    const int tstart = tile * BM;
    if (tstart >= cnt) return;
    const int nrows = min(BM, cnt - tstart);

    const int o0 = blockIdx.x * BN;

    extern __shared__ __align__(128) char smem[];
    const uint32_t sbase = smem_u32(smem);
    int*   s_tok  = (int*)smem;                  // 64 ints
    float* s_scz  = (float*)(smem + 1024);       // 192 floats
    float* s_bias = (float*)(smem + 2048);       // 192 floats

    const int tid  = threadIdx.x;
    const int wid  = tid >> 5;
    const int lane = tid & 31;

    if (tid < BM)
        s_tok[tid] = (tid < nrows) ? g_perm[d][tstart + tid] : -1;
    if (tid < BN) {
        // per-column segment resolution (BN=192 may cross Q/K/V boundaries)
        const int og = o0 + tid;
        const int* qzs; const float* scs; int ogl;
        if (og < Q_DIM) {
            ogl = og; qzs = qz_q + d * (Q_DIM / 8); scs = sc_q + d * Q_DIM;
        } else if (og < Q_DIM + KV_DIM) {
            ogl = og - Q_DIM; qzs = qz_k + d * (KV_DIM / 8); scs = sc_k + d * KV_DIM;
        } else {
            ogl = og - Q_DIM - KV_DIM; qzs = qz_v + d * (KV_DIM / 8); scs = sc_v + d * KV_DIM;
        }
        const int z = (qzs[ogl >> 3] >> ((ogl & 7) * 4)) & 0xF;
        s_scz[tid]  = scs[ogl] * (float)(z + 1);
        s_bias[tid] = bias[og];
    }

    // cp.async source rows (fp16, contiguous); g_wc is contiguous over OUT_DIM
    const __half* xp_base = g_xp + ((size_t)d * XP_ROWS + tstart) * IN_DIM;
    const __half* wc_base = g_wc + ((size_t)d * OUT_DIM + o0) * IN_DIM;
    const int cr  = tid >> 3;    // staging row 0..31 (+32i)
    const int cq  = tid & 7;     // 16B segment within 128B chunk-row

#define ISSUE_COPIES(cc) do {                                                 \
    const uint32_t At = sbase + SM_MISC + ((cc) & 1) * STAGE_B;               \
    const uint32_t Bt = At + TILE_A;                                          \
    _Pragma("unroll")                                                         \
    for (int i = 0; i < 2; i++) {                                             \
        const int r = cr + i * 32;                                            \
        const uint32_t doff = (uint32_t)r * ASTRIDE + cq * 16;                \
        cpa16(At + doff, xp_base + (size_t)r * IN_DIM + (cc) * KC + cq * 8);  \
    }                                                                         \
    _Pragma("unroll")                                                         \
    for (int i = 0; i < 6; i++) {                                             \
        const int r = cr + i * 32;                                            \
        const uint32_t doff = (uint32_t)r * ASTRIDE + cq * 16;                \
        cpa16(Bt + doff, wc_base + (size_t)r * IN_DIM + (cc) * KC + cq * 8);  \
    }                                                                         \
} while (0)

    // warp tiling: 2 (M) x 4 (N); warp computes 32x48
    const int wm  = wid & 1;
    const int wn  = wid >> 1;
    const int l15 = lane & 15;
    const int lq  = lane >> 4;
    const uint32_t a_off0 = (uint32_t)(wm * 32 + l15) * ASTRIDE + lq * 16;
    const uint32_t b_off0 = (uint32_t)(wn * 48 + l15) * ASTRIDE + lq * 16;

    float acc[2][6][4];
    #pragma unroll
    for (int i = 0; i < 2; i++)
        #pragma unroll
        for (int j = 0; j < 6; j++)
            #pragma unroll
            for (int k = 0; k < 4; k++) acc[i][j][k] = 0.f;

    // prologue: fill stage 0
    ISSUE_COPIES(0);
    asm volatile("cp.async.commit_group;" ::: "memory");

    #pragma unroll 1
    for (int c = 0; c < NCHUNK; c++) {
        asm volatile("cp.async.wait_group 0;" ::: "memory");
        __syncthreads();   // stage c landed; all warps done with MMA(c-1)

        if (c + 1 < NCHUNK) ISSUE_COPIES(c + 1);
        asm volatile("cp.async.commit_group;" ::: "memory");

        const uint32_t base = sbase + SM_MISC + (c & 1) * STAGE_B;
        #pragma unroll
        for (int kf = 0; kf < 4; kf++) {
            uint32_t ah[2][4];
            #pragma unroll
            for (int mi = 0; mi < 2; mi++)
                ldsm4(ah[mi], base + a_off0 + mi * (16 * ASTRIDE) + kf * 32);
            uint32_t bh[3][4];
            #pragma unroll
            for (int jj = 0; jj < 3; jj++)
                ldsm4(bh[jj], base + TILE_A + b_off0 + jj * (16 * ASTRIDE) + kf * 32);
            #pragma unroll
            for (int mi = 0; mi < 2; mi++) {
                #pragma unroll
                for (int nf = 0; nf < 6; nf++) {
                    const int jj = nf >> 1, s = nf & 1;
                    mma16816(acc[mi][nf], ah[mi], bh[jj][s], bh[jj][s + 2]);
                }
            }
        }
    }
    __syncthreads();   // misc smem visible; all MMA done

    // ---- epilogue: out = acc + bias - sc*(z+1)*rowsum ----
    #pragma unroll
    for (int mi = 0; mi < 2; mi++) {
        #pragma unroll
        for (int h = 0; h < 2; h++) {
            const int r  = wm * 32 + mi * 16 + h * 8 + (lane >> 2);
            const int tk = s_tok[r];
            if (tk < 0) continue;
            const float rs = g_rowsum[tk];
            float* orow = out + (size_t)tk * OUT_DIM + o0;
            #pragma unroll
            for (int nf = 0; nf < 6; nf++) {
                const int col = wn * 48 + nf * 8 + (lane & 3) * 2;
                float2 v;
                v.x = acc[mi][nf][h * 2 + 0] + s_bias[col]     - s_scz[col]     * rs;
                v.y = acc[mi][nf][h * 2 + 1] + s_bias[col + 1] - s_scz[col + 1] * rs;
                *(float2*)(orow + col) = v;
            }
        }
    }
#undef ISSUE_COPIES
}

extern "C" void kernel_launch(void* const* d_in, const int* in_sizes, int n_in,
                              void* d_out, int out_size) {
    const float* x      = (const float*)d_in[0];
    const float* w_base = (const float*)d_in[1];
    const float* bias   = (const float*)d_in[2];
    const int*   qw_q   = (const int*)d_in[3];
    const int*   qw_k   = (const int*)d_in[4];
    const int*   qw_v   = (const int*)d_in[5];
    const int*   qz_q   = (const int*)d_in[6];
    const int*   qz_k   = (const int*)d_in[7];
    const int*   qz_v   = (const int*)d_in[8];
    const float* sc_q   = (const float*)d_in[9];
    const float* sc_k   = (const float*)d_in[10];
    const float* sc_v   = (const float*)d_in[11];
    const int*   indices = (const int*)d_in[12];
    float* out = (float*)d_out;

    cudaFuncSetAttribute(fused_qkv_delta_mma,
                         cudaFuncAttributeMaxDynamicSharedMemorySize, SMEM_TOTAL);

    setup_kernel<<<1, 1024>>>(indices);
    conv_w_kernel<<<OUT_DIM, 256>>>(w_base, qw_q, qw_k, qw_v, sc_q, sc_k, sc_v);
    {
        dim3 g(XP_ROWS, NUM_D);
        conv_x_kernel<<<g, 256>>>(x);
    }

    dim3 grid(OUT_DIM / BN, NUM_D * NTILE);
    fused_qkv_delta_mma<<<grid, 256, SMEM_TOTAL>>>(
        bias, qz_q, qz_k, qz_v, sc_q, sc_k, sc_v, out);
}

// round 16
// speedup vs baseline: 1.0397x; 1.0397x over previous
#include <cuda_runtime.h>
#include <cuda_fp16.h>
#include <cstdint>

#define T_TOKENS 1024
#define IN_DIM   4096
#define Q_DIM    4096
#define KV_DIM   1024
#define OUT_DIM  6144
#define NUM_D    4

#define BM 64
#define BN 256
#define KC 64
#define NCHUNK (IN_DIM / KC)     // 64
#define NTILE  (T_TOKENS / BM)   // 16 row tiles per adapter
#define NCOL   (OUT_DIM / BN)    // 24 col tiles
#define TOTAL_TILES (NUM_D * NTILE * NCOL)   // 1536 logical tiles
#define NBLOCKS 296              // 148 SMs x 2 resident blocks

#define XP_ROWS (T_TOKENS + BM)  // 1088 padded rows per adapter

#define ASTRIDE 144              // bytes per smem tile row (128 data + 16 pad)
#define TILE_A  (64 * ASTRIDE)   // 9216
#define TILE_BB (256 * ASTRIDE)  // 36864
#define STAGE_B (TILE_A + TILE_BB) // 46080
#define SM_MISC 4096
#define SMEM_TOTAL (SM_MISC + 2 * STAGE_B)   // 96256

__device__ int    g_cnt[NUM_D];
__device__ int    g_perm[NUM_D][T_TOKENS];
__device__ float  g_rowsum[T_TOKENS];
__device__ int    g_tile_ctr;
__device__ __half g_wc[(size_t)NUM_D * OUT_DIM * IN_DIM];   // fp16 combined weights
__device__ __half g_xp[(size_t)NUM_D * XP_ROWS * IN_DIM];   // fp16 permuted x

// ---------------- setup: reset + adapter grouping in one block -------------

__global__ void __launch_bounds__(1024)
setup_kernel(const int* __restrict__ indices) {
    __shared__ int scnt[NUM_D];
    const int t = threadIdx.x;
    if (t == 0) g_tile_ctr = 0;
    if (t < NUM_D) scnt[t] = 0;
    __syncthreads();
    const int d = indices[t];
    const int pos = atomicAdd(&scnt[d], 1);
    g_perm[d][pos] = t;
    __syncthreads();
    if (t < NUM_D) g_cnt[t] = scnt[t];
}

// ------------------------------ helpers -----------------------------------

__device__ __forceinline__ uint32_t smem_u32(const void* p) {
    uint32_t a;
    asm("{ .reg .u64 t; cvta.to.shared.u64 t, %1; cvt.u32.u64 %0, t; }"
        : "=r"(a) : "l"(p));
    return a;
}

__device__ __forceinline__ uint32_t h2pack(float a, float b) {
    __half2 h = __float22half2_rn(make_float2(a, b));
    return *(uint32_t*)&h;
}

__device__ __forceinline__ void cpa16(uint32_t dst, const void* src) {
    asm volatile("cp.async.ca.shared.global [%0], [%1], 16;"
                 :: "r"(dst), "l"(src) : "memory");
}

__device__ __forceinline__ void ldsm4(uint32_t* r, uint32_t addr) {
    asm volatile("ldmatrix.sync.aligned.m8n8.x4.shared.b16 {%0,%1,%2,%3}, [%4];"
                 : "=r"(r[0]), "=r"(r[1]), "=r"(r[2]), "=r"(r[3]) : "r"(addr));
}

__device__ __forceinline__ void mma16816(float* c, const uint32_t* a,
                                         uint32_t b0, uint32_t b1) {
    asm volatile(
        "mma.sync.aligned.m16n8k16.row.col.f32.f16.f16.f32 "
        "{%0,%1,%2,%3}, {%4,%5,%6,%7}, {%8,%9}, {%0,%1,%2,%3};"
        : "+f"(c[0]), "+f"(c[1]), "+f"(c[2]), "+f"(c[3])
        : "r"(a[0]), "r"(a[1]), "r"(a[2]), "r"(a[3]), "r"(b0), "r"(b1));
}

// ---------------- precompute: fp16 combined weights ------------------------

__global__ void __launch_bounds__(256)
conv_w_kernel(const float* __restrict__ w_base,
              const int* __restrict__ qw_q, const int* __restrict__ qw_k,
              const int* __restrict__ qw_v,
              const float* __restrict__ sc_q, const float* __restrict__ sc_k,
              const float* __restrict__ sc_v)
{
    const int o = blockIdx.x;
    const int t = threadIdx.x;
    const float4* wrow = (const float4*)(w_base + (size_t)o * IN_DIM);

    int ol; const int* qws; const float* scs; size_t dq; int ds;
    if (o < Q_DIM) {
        ol = o; qws = qw_q; scs = sc_q; dq = (size_t)Q_DIM * (IN_DIM / 8); ds = Q_DIM;
    } else if (o < Q_DIM + KV_DIM) {
        ol = o - Q_DIM; qws = qw_k; scs = sc_k; dq = (size_t)KV_DIM * (IN_DIM / 8); ds = KV_DIM;
    } else {
        ol = o - Q_DIM - KV_DIM; qws = qw_v; scs = sc_v; dq = (size_t)KV_DIM * (IN_DIM / 8); ds = KV_DIM;
    }

    float4 w[2][2];
    #pragma unroll
    for (int i = 0; i < 2; i++) {
        const int g8 = t + 256 * i;
        w[i][0] = wrow[2 * g8];
        w[i][1] = wrow[2 * g8 + 1];
    }

    #pragma unroll
    for (int d = 0; d < NUM_D; d++) {
        const int* qrow = qws + d * dq + (size_t)ol * (IN_DIM / 8);
        const float s = scs[d * ds + ol];
        __half* dst = g_wc + ((size_t)d * OUT_DIM + o) * IN_DIM;
        #pragma unroll
        for (int i = 0; i < 2; i++) {
            const int g8 = t + 256 * i;
            const int q  = qrow[g8];
            float e0 = fmaf(s, (float)((q      ) & 0xF), w[i][0].x);
            float e1 = fmaf(s, (float)((q >>  4) & 0xF), w[i][0].y);
            float e2 = fmaf(s, (float)((q >>  8) & 0xF), w[i][0].z);
            float e3 = fmaf(s, (float)((q >> 12) & 0xF), w[i][0].w);
            float e4 = fmaf(s, (float)((q >> 16) & 0xF), w[i][1].x);
            float e5 = fmaf(s, (float)((q >> 20) & 0xF), w[i][1].y);
            float e6 = fmaf(s, (float)((q >> 24) & 0xF), w[i][1].z);
            float e7 = fmaf(s, (float)((q >> 28) & 0xF), w[i][1].w);
            uint4 b;
            b.x = h2pack(e0, e1);
            b.y = h2pack(e2, e3);
            b.z = h2pack(e4, e5);
            b.w = h2pack(e6, e7);
            *(uint4*)(dst + (size_t)g8 * 8) = b;
        }
    }
}

// -------- precompute: fp16 permuted activations + fused rowsum -------------

__global__ void __launch_bounds__(256)
conv_x_kernel(const float* __restrict__ x)
{
    const int d = blockIdx.y;
    const int r = blockIdx.x;
    const int cnt  = g_cnt[d];
    const int rcap = (cnt + BM - 1) & ~(BM - 1);
    if (r >= rcap) return;
    const int t = threadIdx.x;
    __half* dst = g_xp + ((size_t)d * XP_ROWS + r) * IN_DIM;
    if (r < cnt) {
        const int tok = g_perm[d][r];
        const float4* src = (const float4*)(x + (size_t)tok * IN_DIM);
        float s = 0.f;
        #pragma unroll
        for (int i = 0; i < 4; i++) {
            float4 v = src[t + 256 * i];
            s += (v.x + v.y) + (v.z + v.w);
            uint2 p;
            p.x = h2pack(v.x, v.y);
            p.y = h2pack(v.z, v.w);
            *(uint2*)(dst + (size_t)(t + 256 * i) * 4) = p;
        }
        __shared__ float red[8];
        #pragma unroll
        for (int off = 16; off > 0; off >>= 1)
            s += __shfl_down_sync(0xffffffffu, s, off);
        if ((t & 31) == 0) red[t >> 5] = s;
        __syncthreads();
        if (t == 0) {
            float tot = 0.f;
            #pragma unroll
            for (int wq = 0; wq < 8; wq++) tot += red[wq];
            g_rowsum[tok] = tot;
        }
    } else {
        #pragma unroll
        for (int i = 0; i < 4; i++)
            *(uint2*)(dst + (size_t)(t + 256 * i) * 4) = make_uint2(0, 0);
    }
}

// --------------------------- main fp16 grouped GEMM ------------------------
// Persistent blocks (296 = 148 SM x 2), atomic tile queue over 1536 logical
// tiles. Per tile: 64(M) x 256(N), KC=64, 2-stage cp.async pipeline,
// warps 2(M) x 4(N), warp tile 32x64.

__global__ void __launch_bounds__(256, 2)
fused_qkv_delta_mma(
    const float* __restrict__ bias,
    const int* __restrict__ qz_q, const int* __restrict__ qz_k, const int* __restrict__ qz_v,
    const float* __restrict__ sc_q, const float* __restrict__ sc_k, const float* __restrict__ sc_v,
    float* __restrict__ out)
{
    extern __shared__ __align__(128) char smem[];
    const uint32_t sbase = smem_u32(smem);
    int*   s_tok  = (int*)smem;                  // 64 ints
    float* s_scz  = (float*)(smem + 1024);       // 256 floats
    float* s_bias = (float*)(smem + 2048);       // 256 floats
    int*   s_next = (int*)(smem + 3072);

    const int tid  = threadIdx.x;
    const int wid  = tid >> 5;
    const int lane = tid & 31;

    // warp tiling: 2 (M) x 4 (N); warp computes 32x64
    const int wm  = wid & 1;
    const int wn  = wid >> 1;
    const int l15 = lane & 15;
    const int lq  = lane >> 4;
    const uint32_t a_off0 = (uint32_t)(wm * 32 + l15) * ASTRIDE + lq * 16;
    const uint32_t b_off0 = (uint32_t)(wn * 64 + l15) * ASTRIDE + lq * 16;

    const int cr = tid >> 3;     // staging row 0..31 (+32i)
    const int cq = tid & 7;      // 16B segment within 128B chunk-row

    for (;;) {
        if (tid == 0) *s_next = atomicAdd(&g_tile_ctr, 1);
        __syncthreads();         // broadcast tile id; also orders prev epilogue
        const int t = *s_next;
        if (t >= TOTAL_TILES) break;

        const int colt = t % NCOL;
        const int rest = t / NCOL;
        const int d    = rest / NTILE;
        const int tile = rest % NTILE;
        const int cnt    = g_cnt[d];
        const int tstart = tile * BM;
        if (tstart >= cnt) continue;
        const int nrows = min(BM, cnt - tstart);

        const int o0 = colt * BN;
        const int* qz; const float* sc; int ol;
        if (o0 < Q_DIM) {
            ol = o0; qz = qz_q + d * (Q_DIM / 8); sc = sc_q + d * Q_DIM;
        } else if (o0 < Q_DIM + KV_DIM) {
            ol = o0 - Q_DIM; qz = qz_k + d * (KV_DIM / 8); sc = sc_k + d * KV_DIM;
        } else {
            ol = o0 - Q_DIM - KV_DIM; qz = qz_v + d * (KV_DIM / 8); sc = sc_v + d * KV_DIM;
        }

        if (tid < BM)
            s_tok[tid] = (tid < nrows) ? g_perm[d][tstart + tid] : -1;
        {
            const int r  = tid;      // one output col each
            const int og = ol + r;
            const int z  = (qz[og >> 3] >> ((og & 7) * 4)) & 0xF;
            s_scz[r]  = sc[og] * (float)(z + 1);
            s_bias[r] = bias[o0 + r];
        }

        const __half* xp_base = g_xp + ((size_t)d * XP_ROWS + tstart) * IN_DIM;
        const __half* wc_base = g_wc + ((size_t)d * OUT_DIM + o0) * IN_DIM;

#define ISSUE_COPIES(cc) do {                                                 \
    const uint32_t At = sbase + SM_MISC + ((cc) & 1) * STAGE_B;               \
    const uint32_t Bt = At + TILE_A;                                          \
    _Pragma("unroll")                                                         \
    for (int i = 0; i < 2; i++) {                                             \
        const int r = cr + i * 32;                                            \
        const uint32_t doff = (uint32_t)r * ASTRIDE + cq * 16;                \
        cpa16(At + doff, xp_base + (size_t)r * IN_DIM + (cc) * KC + cq * 8);  \
    }                                                                         \
    _Pragma("unroll")                                                         \
    for (int i = 0; i < 8; i++) {                                             \
        const int r = cr + i * 32;                                            \
        const uint32_t doff = (uint32_t)r * ASTRIDE + cq * 16;                \
        cpa16(Bt + doff, wc_base + (size_t)r * IN_DIM + (cc) * KC + cq * 8);  \
    }                                                                         \
} while (0)

        float acc[2][8][4];
        #pragma unroll
        for (int i = 0; i < 2; i++)
            #pragma unroll
            for (int j = 0; j < 8; j++)
                #pragma unroll
                for (int k = 0; k < 4; k++) acc[i][j][k] = 0.f;

        ISSUE_COPIES(0);
        asm volatile("cp.async.commit_group;" ::: "memory");

        #pragma unroll 1
        for (int c = 0; c < NCHUNK; c++) {
            asm volatile("cp.async.wait_group 0;" ::: "memory");
            __syncthreads();   // stage c landed; all warps done with MMA(c-1)

            if (c + 1 < NCHUNK) ISSUE_COPIES(c + 1);
            asm volatile("cp.async.commit_group;" ::: "memory");

            const uint32_t base = sbase + SM_MISC + (c & 1) * STAGE_B;
            #pragma unroll
            for (int kf = 0; kf < 4; kf++) {
                uint32_t ah[2][4];
                #pragma unroll
                for (int mi = 0; mi < 2; mi++)
                    ldsm4(ah[mi], base + a_off0 + mi * (16 * ASTRIDE) + kf * 32);
                uint32_t bh[4][4];
                #pragma unroll
                for (int jj = 0; jj < 4; jj++)
                    ldsm4(bh[jj], base + TILE_A + b_off0 + jj * (16 * ASTRIDE) + kf * 32);
                #pragma unroll
                for (int mi = 0; mi < 2; mi++) {
                    #pragma unroll
                    for (int nf = 0; nf < 8; nf++) {
                        const int jj = nf >> 1, s = nf & 1;
                        mma16816(acc[mi][nf], ah[mi], bh[jj][s], bh[jj][s + 2]);
                    }
                }
            }
        }
        __syncthreads();   // misc smem visible; all MMA done

        // ---- epilogue: out = acc + bias - sc*(z+1)*rowsum ----
        #pragma unroll
        for (int mi = 0; mi < 2; mi++) {
            #pragma unroll
            for (int h = 0; h < 2; h++) {
                const int r  = wm * 32 + mi * 16 + h * 8 + (lane >> 2);
                const int tk = s_tok[r];
                if (tk < 0) continue;
                const float rs = g_rowsum[tk];
                float* orow = out + (size_t)tk * OUT_DIM + o0;
                #pragma unroll
                for (int nf = 0; nf < 8; nf++) {
                    const int col = wn * 64 + nf * 8 + (lane & 3) * 2;
                    float2 v;
                    v.x = acc[mi][nf][h * 2 + 0] + s_bias[col]     - s_scz[col]     * rs;
                    v.y = acc[mi][nf][h * 2 + 1] + s_bias[col + 1] - s_scz[col + 1] * rs;
                    *(float2*)(orow + col) = v;
                }
            }
        }
#undef ISSUE_COPIES
    }
}

extern "C" void kernel_launch(void* const* d_in, const int* in_sizes, int n_in,
                              void* d_out, int out_size) {
    const float* x      = (const float*)d_in[0];
    const float* w_base = (const float*)d_in[1];
    const float* bias   = (const float*)d_in[2];
    const int*   qw_q   = (const int*)d_in[3];
    const int*   qw_k   = (const int*)d_in[4];
    const int*   qw_v   = (const int*)d_in[5];
    const int*   qz_q   = (const int*)d_in[6];
    const int*   qz_k   = (const int*)d_in[7];
    const int*   qz_v   = (const int*)d_in[8];
    const float* sc_q   = (const float*)d_in[9];
    const float* sc_k   = (const float*)d_in[10];
    const float* sc_v   = (const float*)d_in[11];
    const int*   indices = (const int*)d_in[12];
    float* out = (float*)d_out;

    cudaFuncSetAttribute(fused_qkv_delta_mma,
                         cudaFuncAttributeMaxDynamicSharedMemorySize, SMEM_TOTAL);

    setup_kernel<<<1, 1024>>>(indices);
    conv_w_kernel<<<OUT_DIM, 256>>>(w_base, qw_q, qw_k, qw_v, sc_q, sc_k, sc_v);
    {
        dim3 g(XP_ROWS, NUM_D);
        conv_x_kernel<<<g, 256>>>(x);
    }

    fused_qkv_delta_mma<<<NBLOCKS, 256, SMEM_TOTAL>>>(
        bias, qz_q, qz_k, qz_v, sc_q, sc_k, sc_v, out);
}